// round 9
// baseline (speedup 1.0000x reference)
#include <cuda_runtime.h>
#include <math.h>

typedef unsigned long long ull;

// Shapes
#define NSEQ_C 8192            // B*W
#define T_CH   48              // chars per word
#define M_C    (NSEQ_C*T_CH)   // 393216 char rows
#define M_M    8192            // B*W msg rows (128*64)

// ---------------- static device scratch (no allocations allowed) ----------------
__device__ float g_xg[301989888ull];        // [2][M][384] gate preacts (char level; msg level reuses low rows)
__device__ float g_out[100663296ull];       // [M][256] BiGRU outputs (char level; msg level reuses rows [0,8192))
__device__ float g_words[2097152ull];       // [8192][256] pooled word vectors / messages (rows [0,128))

// ---------------- helpers ----------------
__device__ __forceinline__ void ffma2(ull &d, ull a, ull b) {
    asm("fma.rn.f32x2 %0, %1, %2, %0;" : "+l"(d) : "l"(a), "l"(b));
}
__device__ __forceinline__ float f2sum(ull v) {
    unsigned lo, hi;
    asm("mov.b64 {%0,%1}, %2;" : "=r"(lo), "=r"(hi) : "l"(v));
    return __uint_as_float(lo) + __uint_as_float(hi);
}
__device__ __forceinline__ float sigmoidf_(float x) { return 1.0f / (1.0f + expf(-x)); }

// ---------------- K1: char input gates, fused embedding gather (K=64) ----------------
// g_xg[dir][m][g] = bih_dir[g] + dot(emb[chars[m]], Wih_dir[g])
__global__ __launch_bounds__(384, 1)
void xg_char_kernel(const int* __restrict__ chars, const float* __restrict__ emb,
                    const float* __restrict__ WihF, const float* __restrict__ WihB,
                    const float* __restrict__ biF,  const float* __restrict__ biB)
{
    const int RB = 96;
    __shared__ __align__(16) float xs[RB][64];
    const int dir = blockIdx.x;
    const int m0  = blockIdx.y * RB;
    const int g   = threadIdx.x;

    const float* W = dir ? WihB : WihF;
    ull w2[32];
    const ull* wrow = (const ull*)(W + (size_t)g * 64);
#pragma unroll
    for (int j = 0; j < 32; j++) w2[j] = wrow[j];
    const float bias = (dir ? biB : biF)[g];

    float4* xs4 = (float4*)xs;
    const float4* emb4 = (const float4*)emb;   // emb rows: 16 float4
    for (int idx = threadIdx.x; idx < RB * 16; idx += 384) {
        int r = idx >> 4, q = idx & 15;
        int ch = chars[m0 + r];
        xs4[idx] = emb4[(size_t)ch * 16 + q];
    }
    __syncthreads();

    float* outp = g_xg + (size_t)dir * M_C * 384 + (size_t)m0 * 384 + g;
#pragma unroll 1
    for (int r = 0; r < RB; r++) {
        const ull* xr = (const ull*)xs[r];
        ull a0 = 0, a1 = 0;
#pragma unroll
        for (int j = 0; j < 32; j += 2) { ffma2(a0, w2[j], xr[j]); ffma2(a1, w2[j + 1], xr[j + 1]); }
        outp[(size_t)r * 384] = f2sum(a0) + f2sum(a1) + bias;
    }
}

// ---------------- K4: message input gates GEMM (K=256) ----------------
// reads g_words [8192][256], writes g_xg[dir][8192][384]
__global__ __launch_bounds__(256, 1)
void xg_k256_kernel(const float* __restrict__ WihF, const float* __restrict__ WihB,
                    const float* __restrict__ biF,  const float* __restrict__ biB)
{
    const int RB = 16;
    __shared__ __align__(16) float xs[RB][256];
    __shared__ float ps[RB][256];
    const int colg = blockIdx.x;              // 0..5 (6*128 = 768 output cols, both dirs)
    const int m0   = blockIdx.y * RB;
    const int tid  = threadIdx.x;
    const int c = tid & 127, kh = tid >> 7;
    const int gcol = colg * 128 + c;
    const int dir  = gcol >= 384;
    const int row  = gcol - dir * 384;

    const float* W = dir ? WihB : WihF;
    ull w2[64];
    const ull* wrow = (const ull*)(W + (size_t)row * 256 + kh * 128);
#pragma unroll
    for (int j = 0; j < 64; j++) w2[j] = wrow[j];

    float4* xs4 = (float4*)xs;
    const float4* X4 = (const float4*)(g_words + (size_t)m0 * 256);
    for (int i = tid; i < RB * 64; i += 256) xs4[i] = X4[i];
    __syncthreads();

#pragma unroll 1
    for (int r = 0; r < RB; r++) {
        const ull* xr = (const ull*)(xs[r] + kh * 128);
        ull a0 = 0, a1 = 0;
#pragma unroll
        for (int j = 0; j < 64; j += 2) { ffma2(a0, w2[j], xr[j]); ffma2(a1, w2[j + 1], xr[j + 1]); }
        ps[r][tid] = f2sum(a0) + f2sum(a1);
    }
    __syncthreads();

    for (int i = tid; i < RB * 128; i += 256) {
        int r = i >> 7, cc = i & 127;
        int gc = colg * 128 + cc; int d2 = gc >= 384; int rw = gc - d2 * 384;
        float v = ps[r][cc] + ps[r][cc + 128] + (d2 ? biB : biF)[rw];
        g_xg[(size_t)d2 * M_M * 384 + (size_t)(m0 + r) * 384 + rw] = v;
    }
}

// ---------------- K2/K5: persistent BiGRU recurrence ----------------
// One block = NB sequences x one direction. Whh row in 64 f32x2 regs/thread,
// h broadcast from SMEM. Masked pad_packed_sequence semantics: state frozen at
// t>=len, outputs zero there; backward direction via index reversal within len.
template <int NB>
__global__ __launch_bounds__(384, 1)
void gru_kernel(const float* __restrict__ WhF, const float* __restrict__ WhB,
                const float* __restrict__ bhF, const float* __restrict__ bhB,
                const int* __restrict__ lens, int nSeq, int T)
{
    __shared__ __align__(16) float hs[NB][128];
    __shared__ float HG[384][NB + 1];
    __shared__ float XN[128][NB + 1];
    __shared__ int   slen[NB];

    const int dir  = blockIdx.x;
    const int seq0 = blockIdx.y * NB;
    const int g    = threadIdx.x;

    const float* W = dir ? WhB : WhF;
    ull w2[64];
    const ull* wrow = (const ull*)(W + (size_t)g * 128);
#pragma unroll
    for (int j = 0; j < 64; j++) w2[j] = wrow[j];
    const float bias = (dir ? bhB : bhF)[g];

    for (int i = g; i < NB * 128; i += 384) ((float*)hs)[i] = 0.f;
    if (g < NB) slen[g] = lens ? lens[seq0 + g] : T;
    const float* xgD = g_xg + (size_t)dir * nSeq * T * 384;
    __syncthreads();

    for (int t = 0; t < T; t++) {
        // phase 1: HG[g][b] = dot(Whh[g], h_b) + bhh[g] (+ xg for r/z rows)
        int lb0 = slen[0];
        int id0 = dir ? ((t < lb0) ? (lb0 - 1 - t) : t) : t;
        float xv = xgD[((size_t)seq0 * T + id0) * 384 + g];
#pragma unroll 1
        for (int b = 0; b < NB; b++) {
            float xnext = 0.f;
            if (b + 1 < NB) {
                int lb = slen[b + 1];
                int idx = dir ? ((t < lb) ? (lb - 1 - t) : t) : t;
                xnext = xgD[((size_t)(seq0 + b + 1) * T + idx) * 384 + g];
            }
            const ull* hr = (const ull*)hs[b];
            ull a0 = 0, a1 = 0;
#pragma unroll
            for (int j = 0; j < 64; j += 2) { ffma2(a0, w2[j], hr[j]); ffma2(a1, w2[j + 1], hr[j + 1]); }
            float hgv = f2sum(a0) + f2sum(a1) + bias;
            if (g < 256) HG[g][b] = xv + hgv;
            else { HG[g][b] = hgv; XN[g - 256][b] = xv; }
            xv = xnext;
        }
        __syncthreads();
        // phase 2: gates + state update + output
        if (g < 128) {
            const int k = g;
#pragma unroll 1
            for (int b = 0; b < NB; b++) {
                int lb = slen[b];
                bool valid = t < lb;
                float r = sigmoidf_(HG[k][b]);
                float z = sigmoidf_(HG[k + 128][b]);
                float n = tanhf(XN[k][b] + r * HG[k + 256][b]);
                float h = hs[b][k];
                float hnew = valid ? ((1.f - z) * n + z * h) : h;
                hs[b][k] = hnew;
                int ot = dir ? (valid ? (lb - 1 - t) : t) : t;
                size_t m = (size_t)(seq0 + b) * T + ot;
                g_out[m * 256 + (size_t)dir * 128 + k] = valid ? hnew : 0.f;
            }
        }
        __syncthreads();
    }
}

// ---------------- K3/K6: attention pooling ----------------
// proj = tanh(out @ Wp^T + bp); att = softmax(proj @ ctx over ALL T); dst = sum att*out.
// One block per sequence. Thread pair (c = tid>>1, kh = tid&1) splits K=256, shfl-combined.
template <int T>
__global__ __launch_bounds__(256, 1)
void attn_kernel(const float* __restrict__ Wp, const float* __restrict__ bp,
                 const float* __restrict__ ctx)
{
    extern __shared__ __align__(16) float sh[];
    float* os = sh;              // T*256
    float* S  = sh + T * 256;    // T*128
    float* av = S + T * 128;     // T
    __shared__ float mv, sv;

    const int word = blockIdx.x, tid = threadIdx.x;
    const int c = tid >> 1, kh = tid & 1;

    const float4* src4 = (const float4*)(g_out + (size_t)word * T * 256);
    float4* os4 = (float4*)os;
    for (int i = tid; i < T * 64; i += 256) os4[i] = src4[i];

    ull w2[64];
    const ull* wr = (const ull*)(Wp + (size_t)c * 256 + kh * 128);
#pragma unroll
    for (int j = 0; j < 64; j++) w2[j] = wr[j];
    const float bb = bp[c], cw = ctx[c];
    __syncthreads();

#pragma unroll 1
    for (int t = 0; t < T; t++) {
        const ull* xr = (const ull*)(os + t * 256 + kh * 128);
        ull a0 = 0, a1 = 0;
#pragma unroll
        for (int j = 0; j < 64; j += 2) { ffma2(a0, w2[j], xr[j]); ffma2(a1, w2[j + 1], xr[j + 1]); }
        float v = f2sum(a0) + f2sum(a1);
        float o = __shfl_xor_sync(0xffffffffu, v, 1);
        if (kh == 0) S[t * 128 + c] = tanhf(v + o + bb) * cw;
    }
    // reduce over c: logits in S[t*128]
    for (int lo = 6; lo >= 0; lo--) {
        __syncthreads();
        int off = 1 << lo;
        for (int i = tid; i < T * off; i += 256) {
            int t = i >> lo, u = i & (off - 1);
            S[t * 128 + u] += S[t * 128 + u + off];
        }
    }
    __syncthreads();
    if (tid == 0) { float m = -1e30f; for (int t = 0; t < T; t++) m = fmaxf(m, S[t * 128]); mv = m; }
    __syncthreads();
    if (tid < T) av[tid] = expf(S[tid * 128] - mv);
    __syncthreads();
    if (tid == 0) { float s = 0.f; for (int t = 0; t < T; t++) s += av[t]; sv = 1.f / s; }
    __syncthreads();
    float acc = 0.f;
#pragma unroll 1
    for (int t = 0; t < T; t++) acc += av[t] * os[t * 256 + tid];
    g_words[(size_t)word * 256 + tid] = acc * sv;
}

// ---------------- K7: output head + writeback ----------------
__global__ __launch_bounds__(256, 1)
void final_kernel(const float* __restrict__ Wout, const float* __restrict__ bout,
                  float* __restrict__ out, int out_size)
{
    const int b = blockIdx.x, tid = threadIdx.x;
    const float* msg = g_words + (size_t)b * 256;
    const bool writeOut = (out_size != 32768);
    const bool writeMsg = (out_size >= 32768);
    const int msgOff = (out_size > 32768) ? 1024 : 0;
    if (writeMsg) out[msgOff + b * 256 + tid] = msg[tid];
    if (writeOut && tid < 8) {
        float acc = bout[tid];
        const float* wr = Wout + tid * 256;
        for (int k = 0; k < 256; k++) acc += msg[k] * wr[k];
        out[b * 8 + tid] = acc;
    }
}

extern "C" void kernel_launch(void* const* d_in, const int* in_sizes, int n_in,
                              void* d_out, int out_size)
{
    const int*   chars  = (const int*)d_in[0];
    const int*   lens   = (const int*)d_in[1];
    const float* emb    = (const float*)d_in[2];
    const float* cWih_f = (const float*)d_in[3];
    const float* cWhh_f = (const float*)d_in[4];
    const float* cbih_f = (const float*)d_in[5];
    const float* cbhh_f = (const float*)d_in[6];
    const float* cWih_b = (const float*)d_in[7];
    const float* cWhh_b = (const float*)d_in[8];
    const float* cbih_b = (const float*)d_in[9];
    const float* cbhh_b = (const float*)d_in[10];
    const float* mWih_f = (const float*)d_in[11];
    const float* mWhh_f = (const float*)d_in[12];
    const float* mbih_f = (const float*)d_in[13];
    const float* mbhh_f = (const float*)d_in[14];
    const float* mWih_b = (const float*)d_in[15];
    const float* mWhh_b = (const float*)d_in[16];
    const float* mbih_b = (const float*)d_in[17];
    const float* mbhh_b = (const float*)d_in[18];
    const float* wWp    = (const float*)d_in[19];
    const float* wbp    = (const float*)d_in[20];
    const float* wctx   = (const float*)d_in[21];
    const float* pWp    = (const float*)d_in[22];
    const float* pbp    = (const float*)d_in[23];
    const float* pctx   = (const float*)d_in[24];
    const float* Wout   = (const float*)d_in[25];
    const float* bout   = (const float*)d_in[26];

    const int sm48 = 48 * 256 * 4 + 48 * 128 * 4 + 48 * 4;   // 73920 B
    const int sm64 = 64 * 256 * 4 + 64 * 128 * 4 + 64 * 4;   // 98560 B
    cudaFuncSetAttribute(attn_kernel<48>, cudaFuncAttributeMaxDynamicSharedMemorySize, sm48);
    cudaFuncSetAttribute(attn_kernel<64>, cudaFuncAttributeMaxDynamicSharedMemorySize, sm64);

    // char level
    xg_char_kernel<<<dim3(2, 4096), 384>>>(chars, emb, cWih_f, cWih_b, cbih_f, cbih_b);
    gru_kernel<16><<<dim3(2, 512), 384>>>(cWhh_f, cWhh_b, cbhh_f, cbhh_b, lens, NSEQ_C, T_CH);
    attn_kernel<48><<<NSEQ_C, 256, sm48>>>(wWp, wbp, wctx);
    // message level
    xg_k256_kernel<<<dim3(6, 512), 256>>>(mWih_f, mWih_b, mbih_f, mbih_b);
    gru_kernel<4><<<dim3(2, 32), 384>>>(mWhh_f, mWhh_b, mbhh_f, mbhh_b, nullptr, 128, 64);
    attn_kernel<64><<<128, 256, sm64>>>(pWp, pbp, pctx);
    // head + writeback
    final_kernel<<<128, 256>>>(Wout, bout, (float*)d_out, out_size);
}

// round 10
// speedup vs baseline: 1.2686x; 1.2686x over previous
#include <cuda_runtime.h>
#include <math.h>

typedef unsigned long long ull;

// Shapes
#define NSEQ_C 8192            // B*W
#define T_CH   48              // chars per word
#define M_C    (NSEQ_C*T_CH)   // 393216 char rows
#define M_M    8192            // msg-level rows used (B*W)

// ---------------- static device scratch (no allocations allowed) ----------------
__device__ float g_xg[301989888ull];        // [2][M][384] gate preacts
__device__ float g_out[100663296ull];       // [M][256] BiGRU outputs
__device__ float g_words[2097152ull];       // [8192][256] pooled word vectors / messages

// ---------------- helpers ----------------
__device__ __forceinline__ void ffma2(ull &d, ull a, ull b) {
    asm("fma.rn.f32x2 %0, %1, %2, %0;" : "+l"(d) : "l"(a), "l"(b));
}
__device__ __forceinline__ float f2sum(ull v) {
    unsigned lo, hi;
    asm("mov.b64 {%0,%1}, %2;" : "=r"(lo), "=r"(hi) : "l"(v));
    return __uint_as_float(lo) + __uint_as_float(hi);
}
__device__ __forceinline__ float sigmoidf_(float x) { return 1.0f / (1.0f + expf(-x)); }

// Load a weight row (K floats) into packed-f32x2 registers via 16B loads.
template <int NU>   // NU = K/4 (number of 16B chunks)
__device__ __forceinline__ void loadW(ull* w2, const float* __restrict__ W) {
    const ulonglong2* wr = (const ulonglong2*)W;
#pragma unroll
    for (int j = 0; j < NU; j++) { ulonglong2 v = wr[j]; w2[2 * j] = v.x; w2[2 * j + 1] = v.y; }
}

// dot(w2[K/2 ulls], x[K floats in shared]) using LDS.128 (2 FFMA2 per shared access),
// 4 independent accumulator chains.
template <int NU>   // NU = K/4
__device__ __forceinline__ float dotT(const ull* w2, const float* xp) {
    const ulonglong2* xr = (const ulonglong2*)xp;
    ull a0 = 0, a1 = 0, a2 = 0, a3 = 0;
#pragma unroll
    for (int j = 0; j < NU; j += 2) {
        ulonglong2 v0 = xr[j];
        ulonglong2 v1 = xr[j + 1];
        ffma2(a0, w2[2 * j],     v0.x);
        ffma2(a1, w2[2 * j + 1], v0.y);
        ffma2(a2, w2[2 * j + 2], v1.x);
        ffma2(a3, w2[2 * j + 3], v1.y);
    }
    return (f2sum(a0) + f2sum(a1)) + (f2sum(a2) + f2sum(a3));
}

// ---------------- K1: char input gates, fused embedding gather (K=64) ----------------
__global__ __launch_bounds__(384, 1)
void xg_char_kernel(const int* __restrict__ chars, const float* __restrict__ emb,
                    const float* __restrict__ WihF, const float* __restrict__ WihB,
                    const float* __restrict__ biF,  const float* __restrict__ biB)
{
    const int RB = 96;
    __shared__ __align__(16) float xs[RB][64];
    const int dir = blockIdx.x;
    const int m0  = blockIdx.y * RB;
    const int g   = threadIdx.x;

    const float* W = dir ? WihB : WihF;
    ull w2[32];
    loadW<16>(w2, W + (size_t)g * 64);
    const float bias = (dir ? biB : biF)[g];

    float4* xs4 = (float4*)xs;
    const float4* emb4 = (const float4*)emb;
    for (int idx = threadIdx.x; idx < RB * 16; idx += 384) {
        int r = idx >> 4, q = idx & 15;
        int ch = chars[m0 + r];
        xs4[idx] = emb4[(size_t)ch * 16 + q];
    }
    __syncthreads();

    float* outp = g_xg + (size_t)dir * M_C * 384 + (size_t)m0 * 384 + g;
#pragma unroll 2
    for (int r = 0; r < RB; r++) {
        outp[(size_t)r * 384] = dotT<16>(w2, xs[r]) + bias;
    }
}

// ---------------- K4: message input gates GEMM (K=256) ----------------
__global__ __launch_bounds__(256, 1)
void xg_k256_kernel(const float* __restrict__ WihF, const float* __restrict__ WihB,
                    const float* __restrict__ biF,  const float* __restrict__ biB)
{
    const int RB = 16;
    __shared__ __align__(16) float xs[RB][256];
    __shared__ float ps[RB][256];
    const int colg = blockIdx.x;              // 0..5
    const int m0   = blockIdx.y * RB;
    const int tid  = threadIdx.x;
    const int c = tid & 127, kh = tid >> 7;   // kh warp-uniform
    const int gcol = colg * 128 + c;
    const int dir  = gcol >= 384;
    const int row  = gcol - dir * 384;

    const float* W = dir ? WihB : WihF;
    ull w2[64];
    loadW<32>(w2, W + (size_t)row * 256 + kh * 128);

    float4* xs4 = (float4*)xs;
    const float4* X4 = (const float4*)(g_words + (size_t)m0 * 256);
    for (int i = tid; i < RB * 64; i += 256) xs4[i] = X4[i];
    __syncthreads();

#pragma unroll 2
    for (int r = 0; r < RB; r++) ps[r][tid] = dotT<32>(w2, xs[r] + kh * 128);
    __syncthreads();

    for (int i = tid; i < RB * 128; i += 256) {
        int r = i >> 7, cc = i & 127;
        int gc = colg * 128 + cc; int d2 = gc >= 384; int rw = gc - d2 * 384;
        float v = ps[r][cc] + ps[r][cc + 128] + (d2 ? biB : biF)[rw];
        g_xg[(size_t)d2 * M_M * 384 + (size_t)(m0 + r) * 384 + rw] = v;
    }
}

// ---------------- K2/K5: persistent BiGRU recurrence ----------------
template <int NB>
__global__ __launch_bounds__(384, 1)
void gru_kernel(const float* __restrict__ WhF, const float* __restrict__ WhB,
                const float* __restrict__ bhF, const float* __restrict__ bhB,
                const int* __restrict__ lens, int nSeq, int T)
{
    __shared__ __align__(16) float hs[NB][128];
    __shared__ float HG[384][NB + 1];
    __shared__ float XN[128][NB + 1];
    __shared__ int   slen[NB];

    const int dir  = blockIdx.x;
    const int seq0 = blockIdx.y * NB;
    const int g    = threadIdx.x;

    const float* W = dir ? WhB : WhF;
    ull w2[64];
    loadW<32>(w2, W + (size_t)g * 128);
    const float bias = (dir ? bhB : bhF)[g];

    for (int i = g; i < NB * 128; i += 384) ((float*)hs)[i] = 0.f;
    if (g < NB) slen[g] = lens ? lens[seq0 + g] : T;
    const float* xgD = g_xg + (size_t)dir * nSeq * T * 384;
    __syncthreads();

    const int k   = g & 127;     // phase-2 mapping
    const int sub = g >> 7;      // 0..2

    for (int t = 0; t < T; t++) {
        // phase 1: HG[g][b] = dot(Whh[g], h_b) + bhh[g] (+ xg for r/z rows)
        int lb0 = slen[0];
        int id0 = dir ? ((t < lb0) ? (lb0 - 1 - t) : t) : t;
        float xv = xgD[((size_t)seq0 * T + id0) * 384 + g];
#pragma unroll 1
        for (int b = 0; b < NB; b++) {
            float xnext = 0.f;
            if (b + 1 < NB) {
                int lb = slen[b + 1];
                int idx = dir ? ((t < lb) ? (lb - 1 - t) : t) : t;
                xnext = xgD[((size_t)(seq0 + b + 1) * T + idx) * 384 + g];
            }
            float hgv = dotT<32>(w2, hs[b]) + bias;
            if (g < 256) HG[g][b] = xv + hgv;
            else { HG[g][b] = hgv; XN[g - 256][b] = xv; }
            xv = xnext;
        }
        __syncthreads();
        // phase 2: gates + state update + output (all 12 warps, 3-way b split)
#pragma unroll 1
        for (int b = sub; b < NB; b += 3) {
            int lb = slen[b];
            bool valid = t < lb;
            float r = sigmoidf_(HG[k][b]);
            float z = sigmoidf_(HG[k + 128][b]);
            float n = tanhf(XN[k][b] + r * HG[k + 256][b]);
            float h = hs[b][k];
            float hnew = valid ? ((1.f - z) * n + z * h) : h;
            hs[b][k] = hnew;
            int ot = dir ? (valid ? (lb - 1 - t) : t) : t;
            size_t m = (size_t)(seq0 + b) * T + ot;
            g_out[m * 256 + (size_t)dir * 128 + k] = valid ? hnew : 0.f;
        }
        __syncthreads();
    }
}

// ---------------- K3/K6: attention pooling ----------------
// proj = tanh(out @ Wp^T + bp); att = softmax(proj @ ctx over ALL T); dst = sum att*out.
// One block/sequence. Warp-uniform K-split: c = tid&127, kh = tid>>7; combine via shared.
template <int T>
__global__ __launch_bounds__(256, 1)
void attn_kernel(const float* __restrict__ Wp, const float* __restrict__ bp,
                 const float* __restrict__ ctx)
{
    extern __shared__ __align__(16) float sh[];
    float* os = sh;                  // T*256
    float* S  = sh + T * 256;        // 2*T*128 partial projections, then logits in S[t*128]
    float* av = S + 2 * T * 128;     // T
    __shared__ float mv, sv;

    const int word = blockIdx.x, tid = threadIdx.x;
    const int c = tid & 127, kh = tid >> 7;

    const float4* src4 = (const float4*)(g_out + (size_t)word * T * 256);
    float4* os4 = (float4*)os;
    for (int i = tid; i < T * 64; i += 256) os4[i] = src4[i];

    ull w2[64];
    loadW<32>(w2, Wp + (size_t)c * 256 + kh * 128);
    __syncthreads();

    float* Sp = S + kh * T * 128 + c;
#pragma unroll 2
    for (int t = 0; t < T; t++) Sp[t * 128] = dotT<32>(w2, os + t * 256 + kh * 128);
    __syncthreads();

    // combine halves, tanh, scale by ctx
    for (int i = tid; i < T * 128; i += 256) {
        int cc = i & 127;
        float v = S[i] + S[T * 128 + i];
        S[i] = tanhf(v + bp[cc]) * ctx[cc];
    }
    // tree-reduce over c: logits -> S[t*128]
    for (int lo = 6; lo >= 0; lo--) {
        __syncthreads();
        int off = 1 << lo;
        for (int i = tid; i < T * off; i += 256) {
            int t = i >> lo, u = i & (off - 1);
            S[t * 128 + u] += S[t * 128 + u + off];
        }
    }
    __syncthreads();
    if (tid == 0) { float m = -1e30f; for (int t = 0; t < T; t++) m = fmaxf(m, S[t * 128]); mv = m; }
    __syncthreads();
    if (tid < T) av[tid] = expf(S[tid * 128] - mv);
    __syncthreads();
    if (tid == 0) { float s = 0.f; for (int t = 0; t < T; t++) s += av[t]; sv = 1.f / s; }
    __syncthreads();
    float acc = 0.f;
#pragma unroll 4
    for (int t = 0; t < T; t++) acc += av[t] * os[t * 256 + tid];
    g_words[(size_t)word * 256 + tid] = acc * sv;
}

// ---------------- K7: output head + writeback ----------------
__global__ __launch_bounds__(256, 1)
void final_kernel(const float* __restrict__ Wout, const float* __restrict__ bout,
                  float* __restrict__ out, int out_size)
{
    const int b = blockIdx.x, tid = threadIdx.x;
    const float* msg = g_words + (size_t)b * 256;
    const bool writeOut = (out_size != 32768);
    const bool writeMsg = (out_size >= 32768);
    const int msgOff = (out_size > 32768) ? 1024 : 0;
    if (writeMsg) out[msgOff + b * 256 + tid] = msg[tid];
    if (writeOut && tid < 8) {
        float acc = bout[tid];
        const float* wr = Wout + tid * 256;
        for (int kk = 0; kk < 256; kk++) acc += msg[kk] * wr[kk];
        out[b * 8 + tid] = acc;
    }
}

extern "C" void kernel_launch(void* const* d_in, const int* in_sizes, int n_in,
                              void* d_out, int out_size)
{
    const int*   chars  = (const int*)d_in[0];
    const int*   lens   = (const int*)d_in[1];
    const float* emb    = (const float*)d_in[2];
    const float* cWih_f = (const float*)d_in[3];
    const float* cWhh_f = (const float*)d_in[4];
    const float* cbih_f = (const float*)d_in[5];
    const float* cbhh_f = (const float*)d_in[6];
    const float* cWih_b = (const float*)d_in[7];
    const float* cWhh_b = (const float*)d_in[8];
    const float* cbih_b = (const float*)d_in[9];
    const float* cbhh_b = (const float*)d_in[10];
    const float* mWih_f = (const float*)d_in[11];
    const float* mWhh_f = (const float*)d_in[12];
    const float* mbih_f = (const float*)d_in[13];
    const float* mbhh_f = (const float*)d_in[14];
    const float* mWih_b = (const float*)d_in[15];
    const float* mWhh_b = (const float*)d_in[16];
    const float* mbih_b = (const float*)d_in[17];
    const float* mbhh_b = (const float*)d_in[18];
    const float* wWp    = (const float*)d_in[19];
    const float* wbp    = (const float*)d_in[20];
    const float* wctx   = (const float*)d_in[21];
    const float* pWp    = (const float*)d_in[22];
    const float* pbp    = (const float*)d_in[23];
    const float* pctx   = (const float*)d_in[24];
    const float* Wout   = (const float*)d_in[25];
    const float* bout   = (const float*)d_in[26];

    const int sm48 = (48 * 256 + 2 * 48 * 128 + 48) * 4;   // 98496 B
    const int sm64 = (64 * 256 + 2 * 64 * 128 + 64) * 4;   // 131328 B
    cudaFuncSetAttribute(attn_kernel<48>, cudaFuncAttributeMaxDynamicSharedMemorySize, sm48);
    cudaFuncSetAttribute(attn_kernel<64>, cudaFuncAttributeMaxDynamicSharedMemorySize, sm64);

    // char level
    xg_char_kernel<<<dim3(2, 4096), 384>>>(chars, emb, cWih_f, cWih_b, cbih_f, cbih_b);
    gru_kernel<16><<<dim3(2, 512), 384>>>(cWhh_f, cWhh_b, cbhh_f, cbhh_b, lens, NSEQ_C, T_CH);
    attn_kernel<48><<<NSEQ_C, 256, sm48>>>(wWp, wbp, wctx);
    // message level
    xg_k256_kernel<<<dim3(6, 512), 256>>>(mWih_f, mWih_b, mbih_f, mbih_b);
    gru_kernel<4><<<dim3(2, 32), 384>>>(mWhh_f, mWhh_b, mbhh_f, mbhh_b, nullptr, 128, 64);
    attn_kernel<64><<<128, 256, sm64>>>(pWp, pbp, pctx);
    // head + writeback
    final_kernel<<<128, 256>>>(Wout, bout, (float*)d_out, out_size);
}